// round 15
// baseline (speedup 1.0000x reference)
#include <cuda_runtime.h>
#include <cuda_fp16.h>
#include <cstdint>

#define DIMC   1024
#define NHEAD  16
#define HDIM   64
#define BATCH  2
#define MAXT   2048
#define MAXM   (BATCH * MAXT)

// q scale folded into Q at QKV epilogue: 1/sqrt(64) * log2(e)
#define QSCALE (0.125f * 1.4426950408889634f)

// Packed-tile geometry for GEMM: A block = 128x32 (64B rows, swizzled) = 8KB
//                                B block = 256x32 = 16KB
#define ABLKB 8192
#define BBLKB 16384

// Scratch (__device__ globals; no cudaMalloc allowed). 128B-aligned for bulk DMA.
__device__ __align__(128) __half g_xA[(size_t)MAXM * DIMC];        // packed A (QKV)
__device__ __align__(128) __half g_wqkvB[(size_t)3 * DIMC * DIMC]; // packed B (QKV)
__device__ __align__(128) __half g_wprojB[(size_t)DIMC * DIMC];    // packed B (proj)
// per-head packed QKV: [b][h][sec 0..2][t][64 halves], dense 128B rows, XOR swizzle
__device__ __align__(128) __half g_qkvP[(size_t)BATCH * NHEAD * 3 * MAXT * HDIM];
__device__ __align__(128) __half g_attnP[(size_t)MAXM * DIMC];     // packed A (proj)

// ---------------------------------------------------------------------------
// helpers
// ---------------------------------------------------------------------------
__device__ __forceinline__ uint32_t smem_u32(const void* p) {
    uint32_t a;
    asm("{ .reg .u64 t; cvta.to.shared.u64 t, %1; cvt.u32.u64 %0, t; }" : "=r"(a) : "l"(p));
    return a;
}

#define CP_BULK(dst_u32, src_ptr, nbytes, mbar_u32) \
    asm volatile("cp.async.bulk.shared::cluster.global.mbarrier::complete_tx::bytes " \
                 "[%0], [%1], %2, [%3];" \
                 :: "r"(dst_u32), "l"(src_ptr), "r"(nbytes), "r"(mbar_u32) : "memory")

#define MBARRIER_INIT(addr, cnt) \
    asm volatile("mbarrier.init.shared.b64 [%0], %1;" :: "r"(addr), "r"(cnt) : "memory")
#define MBARRIER_EXPECT_TX(addr, tx) \
    asm volatile("mbarrier.arrive.expect_tx.shared.b64 _, [%0], %1;" \
                 :: "r"(addr), "r"(tx) : "memory")
#define MBARRIER_WAIT_PARITY(addr, par) do {                                        \
    uint32_t _m = (addr), _p = (par), _d;                                           \
    asm volatile("{\n\t.reg .pred p;\n\t"                                           \
        "mbarrier.try_wait.parity.acquire.cta.shared::cta.b64 p, [%1], %2;\n\t"     \
        "selp.b32 %0, 1, 0, p;\n\t}" : "=r"(_d) : "r"(_m), "r"(_p) : "memory");     \
    if (!_d) {                                                                      \
        asm volatile("{\n\t.reg .pred P1;\n\tWL_%=:\n\t"                            \
            "mbarrier.try_wait.parity.acquire.cta.shared::cta.b64 P1, [%0], %1, 0x989680;\n\t" \
            "@P1 bra.uni WD_%=;\n\tbra.uni WL_%=;\n\tWD_%=:\n\t}"                   \
            :: "r"(_m), "r"(_p) : "memory");                                        \
    }                                                                               \
} while (0)

__device__ __forceinline__ void mma_f16(float* d, const unsigned* a,
                                        unsigned b0, unsigned b1) {
    asm volatile(
        "mma.sync.aligned.m16n8k16.row.col.f32.f16.f16.f32 "
        "{%0,%1,%2,%3}, {%4,%5,%6,%7}, {%8,%9}, {%0,%1,%2,%3};\n"
        : "+f"(d[0]), "+f"(d[1]), "+f"(d[2]), "+f"(d[3])
        : "r"(a[0]), "r"(a[1]), "r"(a[2]), "r"(a[3]), "r"(b0), "r"(b1));
}

__device__ __forceinline__ void ldmx4(unsigned* r, uint32_t addr) {
    asm volatile("ldmatrix.sync.aligned.m8n8.x4.shared.b16 {%0,%1,%2,%3}, [%4];"
                 : "=r"(r[0]), "=r"(r[1]), "=r"(r[2]), "=r"(r[3]) : "r"(addr));
}
__device__ __forceinline__ void ldmx4t(unsigned* r, uint32_t addr) {
    asm volatile("ldmatrix.sync.aligned.m8n8.x4.trans.shared.b16 {%0,%1,%2,%3}, [%4];"
                 : "=r"(r[0]), "=r"(r[1]), "=r"(r[2]), "=r"(r[3]) : "r"(addr));
}

__device__ __forceinline__ unsigned pack2(float x, float y) {
    __half2 h = __floats2half2_rn(x, y);
    return *reinterpret_cast<unsigned*>(&h);
}
__device__ __forceinline__ float ex2f(float x) {
    float y;
    asm("ex2.approx.f32 %0, %1;" : "=f"(y) : "f"(x));
    return y;
}

// ---------------------------------------------------------------------------
// Packers (GEMM operands): write (row, col) at row*64 + (col_bytes ^ xorv(row)),
// xorv(row) = ((row>>1)&3)<<4.
// ---------------------------------------------------------------------------
__global__ __launch_bounds__(256) void xpack_kernel(const float* __restrict__ x) {
    const int kc = blockIdx.x, mb = blockIdx.y;
    const int tid = threadIdx.x;
    const int r = tid >> 1, hf = tid & 1;
    const float* src = x + (size_t)(mb * 128 + r) * DIMC + kc * 32 + hf * 16;
    float4 v0 = *reinterpret_cast<const float4*>(src);
    float4 v1 = *reinterpret_cast<const float4*>(src + 4);
    float4 v2 = *reinterpret_cast<const float4*>(src + 8);
    float4 v3 = *reinterpret_cast<const float4*>(src + 12);
    uint4 u0 = make_uint4(pack2(v0.x, v0.y), pack2(v0.z, v0.w),
                          pack2(v1.x, v1.y), pack2(v1.z, v1.w));
    uint4 u1 = make_uint4(pack2(v2.x, v2.y), pack2(v2.z, v2.w),
                          pack2(v3.x, v3.y), pack2(v3.z, v3.w));
    const uint32_t xorv = ((r >> 1) & 3) << 4;
    char* dst = (char*)g_xA + (size_t)(mb * 32 + kc) * ABLKB + r * 64;
    *reinterpret_cast<uint4*>(dst + ((hf * 32)      ^ xorv)) = u0;
    *reinterpret_cast<uint4*>(dst + ((hf * 32 + 16) ^ xorv)) = u1;
}

__global__ __launch_bounds__(256) void wpack_kernel(const float* __restrict__ W,
                                                    __half* __restrict__ out, int N) {
    const int nb = blockIdx.x, kc = blockIdx.y;
    const int n = threadIdx.x;
    __half h[32];
    #pragma unroll
    for (int k = 0; k < 32; k++)
        h[k] = __float2half_rn(W[(size_t)(kc * 32 + k) * N + nb * 256 + n]);
    const uint32_t xorv = ((n >> 1) & 3) << 4;
    char* dst = (char*)out + (size_t)(nb * 32 + kc) * BBLKB + n * 64;
    const uint4* hu = reinterpret_cast<const uint4*>(h);
    #pragma unroll
    for (int u = 0; u < 4; u++)
        *reinterpret_cast<uint4*>(dst + ((u * 16) ^ xorv)) = hu[u];
}

// ---------------------------------------------------------------------------
// Bulk-DMA fp16 GEMM + bias (R14-proven core). out_mode: 0 = fp32 row-major,
// 1 = packed per-head QKV layout (g_qkvP) with Q columns pre-scaled.
// ---------------------------------------------------------------------------
#define STAGEB   (ABLKB + BBLKB)       // 24576
#define NBUF     6
#define MBAR_OFF (NBUF * STAGEB)       // 147456
#define G_SMEM   (MBAR_OFF + 64)

__global__ __launch_bounds__(256, 1) void gemm_bulk_kernel(
    const __half* __restrict__ Apack, const __half* __restrict__ Bpack,
    const float* __restrict__ bias, void* __restrict__ Cout,
    int N, int out_mode)
{
    extern __shared__ char smraw[];
    const uint32_t s0 = smem_u32(smraw);

    const int tid  = threadIdx.x;
    const int lane = tid & 31;
    const int warp = tid >> 5;
    const int wr = (warp >> 2) * 64;
    const int wc = (warp & 3) * 64;
    const int mb = blockIdx.y, nb = blockIdx.x;
    const int row0 = mb * 128, col0 = nb * 256;

    if (tid == 0) {
        #pragma unroll
        for (int s = 0; s < NBUF; s++) MBARRIER_INIT(s0 + MBAR_OFF + 8 * s, 1);
    }
    __syncthreads();

    float acc[4][8][4];
    #pragma unroll
    for (int mt = 0; mt < 4; mt++)
        #pragma unroll
        for (int nt = 0; nt < 8; nt++)
            #pragma unroll
            for (int i = 0; i < 4; i++) acc[mt][nt][i] = 0.f;

    const char* Abase = (const char*)Apack + (size_t)mb * 32 * ABLKB;
    const char* Bbase = (const char*)Bpack + (size_t)nb * 32 * BBLKB;

    auto stage = [&](int kc) {
        const int buf = kc % NBUF;
        const uint32_t mbar = s0 + MBAR_OFF + 8 * buf;
        const uint32_t dst  = s0 + buf * STAGEB;
        MBARRIER_EXPECT_TX(mbar, STAGEB);
        CP_BULK(dst,         Abase + (size_t)kc * ABLKB, ABLKB, mbar);
        CP_BULK(dst + ABLKB, Bbase + (size_t)kc * BBLKB, BBLKB, mbar);
    };

    const int f_row = lane & 15;
    const uint32_t cb = (lane >> 4) << 4;
    uint32_t rbA[4], xvA[4], rbB[4], xvB[4];
    #pragma unroll
    for (int i = 0; i < 4; i++) {
        const int rA = wr + i * 16 + f_row;
        const int rB = wc + i * 16 + f_row;
        rbA[i] = rA * 64;          xvA[i] = ((rA >> 1) & 3) << 4;
        rbB[i] = ABLKB + rB * 64;  xvB[i] = ((rB >> 1) & 3) << 4;
    }

    auto compute = [&](uint32_t base) {
        #pragma unroll
        for (int ks = 0; ks < 2; ks++) {
            const uint32_t col = ks * 32 + cb;
            unsigned af[4][4], bf[4][4];
            #pragma unroll
            for (int mt = 0; mt < 4; mt++)
                ldmx4(af[mt], base + rbA[mt] + (col ^ xvA[mt]));
            #pragma unroll
            for (int ntp = 0; ntp < 4; ntp++)
                ldmx4(bf[ntp], base + rbB[ntp] + (col ^ xvB[ntp]));
            #pragma unroll
            for (int mt = 0; mt < 4; mt++)
                #pragma unroll
                for (int ntp = 0; ntp < 4; ntp++) {
                    mma_f16(acc[mt][2 * ntp],     af[mt], bf[ntp][0], bf[ntp][2]);
                    mma_f16(acc[mt][2 * ntp + 1], af[mt], bf[ntp][1], bf[ntp][3]);
                }
        }
    };

    if (tid == 0) { stage(0); stage(1); stage(2); stage(3); }

    int par[NBUF] = {0, 0, 0, 0, 0, 0};
    for (int i = 0; i < 32; i += 2) {
        const int b0 = i % NBUF, b1 = (i + 1) % NBUF;
        MBARRIER_WAIT_PARITY(s0 + MBAR_OFF + 8 * b0, par[b0]); par[b0] ^= 1;
        MBARRIER_WAIT_PARITY(s0 + MBAR_OFF + 8 * b1, par[b1]); par[b1] ^= 1;
        __syncthreads();
        if (tid == 0) {
            if (i + 4 < 32) stage(i + 4);
            if (i + 5 < 32) stage(i + 5);
        }
        compute(s0 + b0 * STAGEB);
        compute(s0 + b1 * STAGEB);
    }

    const int g = lane >> 2, t = lane & 3;
    #pragma unroll
    for (int mt = 0; mt < 4; mt++) {
        const int r0 = row0 + wr + mt * 16 + g;
        #pragma unroll
        for (int nt = 0; nt < 8; nt++) {
            const int c = col0 + wc + nt * 8 + 2 * t;
            const float b0v = bias[c], b1v = bias[c + 1];
            if (out_mode == 1) {
                // packed per-head QKV: sec/h/d decomposition, swizzled 128B rows
                const int sec = c >> 10;
                const int h   = (c >> 6) & 15;
                const int d   = c & 63;
                const float qs = (sec == 0) ? QSCALE : 1.f;
                const uint32_t cb2 = d * 2;
                #pragma unroll
                for (int rr = 0; rr < 2; rr++) {
                    const int r = r0 + rr * 8;
                    const int bb = r >> 11, tt = r & 2047;
                    char* bp = (char*)g_qkvP +
                        ((((size_t)(bb * NHEAD + h) * 3 + sec) * MAXT + tt) * 128);
                    const uint32_t off = (cb2 & 15) | ((cb2 & 0x70) ^ ((tt & 7) << 4));
                    *reinterpret_cast<__half2*>(bp + off) =
                        __floats2half2_rn((acc[mt][nt][2 * rr]     + b0v) * qs,
                                          (acc[mt][nt][2 * rr + 1] + b1v) * qs);
                }
            } else {
                float* Cf = (float*)Cout;
                *reinterpret_cast<float2*>(&Cf[(size_t)r0 * N + c]) =
                    make_float2(acc[mt][nt][0] + b0v, acc[mt][nt][1] + b1v);
                *reinterpret_cast<float2*>(&Cf[(size_t)(r0 + 8) * N + c]) =
                    make_float2(acc[mt][nt][2] + b0v, acc[mt][nt][3] + b1v);
            }
        }
    }
}

// ---------------------------------------------------------------------------
// Causal flash attention, ALL-BULK staging: Q (16KB) and K/V tiles (8+8KB)
// via cp.async.bulk + mbarrier from the per-head packed g_qkvP. Causal
// pairing, 4 warps, register P, log2 softmax. Dense 128B rows + XOR swizzle
// (per-lane constant). Epilogue writes packed A for proj (g_attnP).
// ---------------------------------------------------------------------------
#define KVTILEB  8192                      // 64 rows x 128B
#define AQ_OFF   0                         // Q: 128 rows x 128B = 16KB
#define AKV_OFF  16384
#define AKV_STG  (2 * KVTILEB)             // K + V per stage = 16KB
#define AMB_OFF  (AKV_OFF + 3 * AKV_STG)   // 65536
#define AT_SMEM  (AMB_OFF + 64)            // 65600 -> 2 CTA/SM

__global__ __launch_bounds__(128, 1) void attn_f16_kernel(int T)
{
    extern __shared__ char smraw[];
    const uint32_t s0 = smem_u32(smraw);

    const int pair = blockIdx.x;
    const int nq   = gridDim.x * 2;
    const int h    = blockIdx.y;
    const int b    = blockIdx.z;
    const int tid  = threadIdx.x;
    const int lane = tid & 31;
    const int warp = tid >> 5;
    const int g = lane >> 2;
    const int t = lane & 3;

    const int rb = warp * 32;

    if (tid == 0) {
        MBARRIER_INIT(s0 + AMB_OFF, 1);           // Q
        MBARRIER_INIT(s0 + AMB_OFF + 8, 1);       // KV buf 0
        MBARRIER_INIT(s0 + AMB_OFF + 16, 1);      // KV buf 1
        MBARRIER_INIT(s0 + AMB_OFF + 24, 1);      // KV buf 2
    }
    __syncthreads();

    // per-head packed bases (bytes)
    const char* qkvBase = (const char*)g_qkvP +
        (size_t)(b * NHEAD + h) * 3 * MAXT * 128;
    const char* Qg = qkvBase;                       // sec 0
    const char* Kg = qkvBase + (size_t)MAXT * 128;  // sec 1
    const char* Vg = Kg + (size_t)MAXT * 128;       // sec 2

    // per-lane fragment addressing constants
    const int f_row = lane & 15;
    const uint32_t cbb = (lane >> 4) << 4;             // 0/16 bytes
    const uint32_t xq  = (f_row & 7) << 4;
    const int v_row = ((lane >> 3) & 1) * 8 + (lane & 7);
    const uint32_t vcb = (lane >> 4) << 4;
    const uint32_t xv  = (v_row & 7) << 4;

    auto stageKV = [&](int kv0, int buf) {
        const uint32_t mbar = s0 + AMB_OFF + 8 + 8 * buf;
        const uint32_t dst  = s0 + AKV_OFF + buf * AKV_STG;
        MBARRIER_EXPECT_TX(mbar, AKV_STG);
        CP_BULK(dst,           Kg + (size_t)kv0 * 128, KVTILEB, mbar);
        CP_BULK(dst + KVTILEB, Vg + (size_t)kv0 * 128, KVTILEB, mbar);
    };

    int parKV[3] = {0, 0, 0};
    int parQ = 0;

    for (int sub = 0; sub < 2; sub++) {
        const int qt = sub ? (nq - 1 - pair) : pair;
        const int q0 = qt * 128;
        const int nkv = 2 * qt + 2;

        __syncthreads();   // previous sub-tile's smem reads complete

        if (tid == 0) {
            MBARRIER_EXPECT_TX(s0 + AMB_OFF, 16384);
            CP_BULK(s0 + AQ_OFF, Qg + (size_t)q0 * 128, 16384, s0 + AMB_OFF);
            stageKV(0, 0);
            stageKV(64, 1);
        }

        MBARRIER_WAIT_PARITY(s0 + AMB_OFF, parQ); parQ ^= 1;

        unsigned qf[4][2][4];   // [ks][mt]
        #pragma unroll
        for (int ks = 0; ks < 4; ks++)
            #pragma unroll
            for (int mt = 0; mt < 2; mt++)
                ldmx4(qf[ks][mt],
                      s0 + AQ_OFF + (rb + mt * 16 + f_row) * 128 + ((ks * 32 + cbb) ^ xq));

        float o[2][8][4];
        #pragma unroll
        for (int mt = 0; mt < 2; mt++)
            #pragma unroll
            for (int nt = 0; nt < 8; nt++)
                #pragma unroll
                for (int i = 0; i < 4; i++) o[mt][nt][i] = 0.f;

        float mx[2][2], ls[2][2];
        #pragma unroll
        for (int mt = 0; mt < 2; mt++) { mx[mt][0] = mx[mt][1] = -1e30f; ls[mt][0] = ls[mt][1] = 0.f; }

        for (int kt_i = 0; kt_i < nkv; kt_i++) {
            const int buf = kt_i % 3;
            MBARRIER_WAIT_PARITY(s0 + AMB_OFF + 8 + 8 * buf, parKV[buf]); parKV[buf] ^= 1;
            __syncthreads();   // prior reads of buf (kt_i-3) done before restage below
            if (tid == 0 && kt_i + 2 < nkv) stageKV((kt_i + 2) * 64, (kt_i + 2) % 3);

            const uint32_t kb = s0 + AKV_OFF + buf * AKV_STG;
            const uint32_t vb = kb + KVTILEB;
            const int kv0 = kt_i * 64;

            // ---- S = Q @ K^T
            float s[2][8][4];
            #pragma unroll
            for (int mt = 0; mt < 2; mt++)
                #pragma unroll
                for (int nt = 0; nt < 8; nt++)
                    #pragma unroll
                    for (int i = 0; i < 4; i++) s[mt][nt][i] = 0.f;

            #pragma unroll
            for (int ks = 0; ks < 4; ks++) {
                #pragma unroll
                for (int ntp = 0; ntp < 4; ntp++) {
                    unsigned kf[4];
                    ldmx4(kf, kb + (ntp * 16 + f_row) * 128 + ((ks * 32 + cbb) ^ xq));
                    #pragma unroll
                    for (int mt = 0; mt < 2; mt++) {
                        mma_f16(s[mt][2 * ntp],     qf[ks][mt], kf[0], kf[2]);
                        mma_f16(s[mt][2 * ntp + 1], qf[ks][mt], kf[1], kf[3]);
                    }
                }
            }

            // ---- causal mask + log2-domain online softmax
            const bool do_mask = (kt_i >= 2 * qt);
            #pragma unroll
            for (int mt = 0; mt < 2; mt++) {
                const int rg0 = q0 + rb + mt * 16 + g;
                const int rg1 = rg0 + 8;
                float m0loc = -1e30f, m1loc = -1e30f;
                #pragma unroll
                for (int nt = 0; nt < 8; nt++) {
                    const int j = kv0 + nt * 8 + 2 * t;
                    if (do_mask) {
                        #pragma unroll
                        for (int c = 0; c < 2; c++) {
                            if (j + c > rg0) s[mt][nt][c]     = -1e30f;
                            if (j + c > rg1) s[mt][nt][c + 2] = -1e30f;
                        }
                    }
                    m0loc = fmaxf(m0loc, fmaxf(s[mt][nt][0], s[mt][nt][1]));
                    m1loc = fmaxf(m1loc, fmaxf(s[mt][nt][2], s[mt][nt][3]));
                }
                m0loc = fmaxf(m0loc, __shfl_xor_sync(0xffffffffu, m0loc, 1));
                m0loc = fmaxf(m0loc, __shfl_xor_sync(0xffffffffu, m0loc, 2));
                m1loc = fmaxf(m1loc, __shfl_xor_sync(0xffffffffu, m1loc, 1));
                m1loc = fmaxf(m1loc, __shfl_xor_sync(0xffffffffu, m1loc, 2));

                const float m0n = fmaxf(mx[mt][0], m0loc);
                const float m1n = fmaxf(mx[mt][1], m1loc);
                const float corr0 = ex2f(mx[mt][0] - m0n);
                const float corr1 = ex2f(mx[mt][1] - m1n);

                float l0loc = 0.f, l1loc = 0.f;
                #pragma unroll
                for (int nt = 0; nt < 8; nt++) {
                    float p00 = ex2f(s[mt][nt][0] - m0n);
                    float p01 = ex2f(s[mt][nt][1] - m0n);
                    float p10 = ex2f(s[mt][nt][2] - m1n);
                    float p11 = ex2f(s[mt][nt][3] - m1n);
                    l0loc += p00 + p01;
                    l1loc += p10 + p11;
                    s[mt][nt][0] = p00; s[mt][nt][1] = p01;
                    s[mt][nt][2] = p10; s[mt][nt][3] = p11;
                }
                l0loc += __shfl_xor_sync(0xffffffffu, l0loc, 1);
                l0loc += __shfl_xor_sync(0xffffffffu, l0loc, 2);
                l1loc += __shfl_xor_sync(0xffffffffu, l1loc, 1);
                l1loc += __shfl_xor_sync(0xffffffffu, l1loc, 2);

                ls[mt][0] = ls[mt][0] * corr0 + l0loc;
                ls[mt][1] = ls[mt][1] * corr1 + l1loc;
                mx[mt][0] = m0n; mx[mt][1] = m1n;

                #pragma unroll
                for (int nt = 0; nt < 8; nt++) {
                    o[mt][nt][0] *= corr0; o[mt][nt][1] *= corr0;
                    o[mt][nt][2] *= corr1; o[mt][nt][3] *= corr1;
                }
            }

            // ---- O += P @ V   (V B-frags via ldmatrix.trans on dense rows)
            #pragma unroll
            for (int ks = 0; ks < 4; ks++) {
                unsigned pa[2][4];
                #pragma unroll
                for (int mt = 0; mt < 2; mt++) {
                    pa[mt][0] = pack2(s[mt][2 * ks][0],     s[mt][2 * ks][1]);
                    pa[mt][1] = pack2(s[mt][2 * ks][2],     s[mt][2 * ks][3]);
                    pa[mt][2] = pack2(s[mt][2 * ks + 1][0], s[mt][2 * ks + 1][1]);
                    pa[mt][3] = pack2(s[mt][2 * ks + 1][2], s[mt][2 * ks + 1][3]);
                }
                #pragma unroll
                for (int ntp = 0; ntp < 4; ntp++) {
                    unsigned vf[4];
                    ldmx4t(vf, vb + (ks * 16 + v_row) * 128 + ((ntp * 32 + vcb) ^ xv));
                    #pragma unroll
                    for (int mt = 0; mt < 2; mt++) {
                        mma_f16(o[mt][2 * ntp],     pa[mt], vf[0], vf[1]);
                        mma_f16(o[mt][2 * ntp + 1], pa[mt], vf[2], vf[3]);
                    }
                }
            }
        }

        // ---- epilogue: packed+swizzled A tiles for the proj GEMM (64B rows)
        const int mbA = (b * T + q0) >> 7;
        #pragma unroll
        for (int mt = 0; mt < 2; mt++) {
            const float inv0 = 1.f / ls[mt][0];
            const float inv1 = 1.f / ls[mt][1];
            const int r0 = rb + mt * 16 + g;
            const int r1 = r0 + 8;
            const uint32_t xv0 = ((r0 >> 1) & 3) << 4;
            const uint32_t xv1 = ((r1 >> 1) & 3) << 4;
            #pragma unroll
            for (int nt = 0; nt < 8; nt++) {
                const int d = nt * 8 + 2 * t;
                const int kcA = (h << 1) + (d >> 5);
                const uint32_t cbyte = (d & 31) * 2;
                char* bp = (char*)g_attnP + (size_t)(mbA * 32 + kcA) * ABLKB;
                *reinterpret_cast<__half2*>(bp + r0 * 64 + (cbyte ^ xv0)) =
                    __floats2half2_rn(o[mt][nt][0] * inv0, o[mt][nt][1] * inv0);
                *reinterpret_cast<__half2*>(bp + r1 * 64 + (cbyte ^ xv1)) =
                    __floats2half2_rn(o[mt][nt][2] * inv1, o[mt][nt][3] * inv1);
            }
        }
    }
}

// ---------------------------------------------------------------------------
// Launch
// ---------------------------------------------------------------------------
extern "C" void kernel_launch(void* const* d_in, const int* in_sizes, int n_in,
                              void* d_out, int out_size)
{
    const float* x      = (const float*)d_in[0];
    const float* W_qkv  = (const float*)d_in[1];
    const float* b_qkv  = (const float*)d_in[2];
    const float* W_proj = (const float*)d_in[3];
    const float* b_proj = (const float*)d_in[4];
    float* out = (float*)d_out;

    const int M = in_sizes[0] / DIMC;   // 4096
    const int T = M / BATCH;            // 2048

    __half *xA, *wqkvB, *wprojB, *attnP;
    cudaGetSymbolAddress((void**)&xA,     g_xA);
    cudaGetSymbolAddress((void**)&wqkvB,  g_wqkvB);
    cudaGetSymbolAddress((void**)&wprojB, g_wprojB);
    cudaGetSymbolAddress((void**)&attnP,  g_attnP);

    static cudaStream_t s1 = nullptr, s2 = nullptr;
    static cudaEvent_t evRoot, evQkvW, evProjW;
    if (!s1) {
        cudaStreamCreateWithFlags(&s1, cudaStreamNonBlocking);
        cudaStreamCreateWithFlags(&s2, cudaStreamNonBlocking);
        cudaEventCreateWithFlags(&evRoot,  cudaEventDisableTiming);
        cudaEventCreateWithFlags(&evQkvW,  cudaEventDisableTiming);
        cudaEventCreateWithFlags(&evProjW, cudaEventDisableTiming);
        cudaFuncSetAttribute(gemm_bulk_kernel,
                             cudaFuncAttributeMaxDynamicSharedMemorySize, G_SMEM);
        cudaFuncSetAttribute(attn_f16_kernel,
                             cudaFuncAttributeMaxDynamicSharedMemorySize, AT_SMEM);
    }

    // fork packers
    cudaEventRecord(evRoot, 0);
    cudaStreamWaitEvent(s1, evRoot, 0);
    cudaStreamWaitEvent(s2, evRoot, 0);

    xpack_kernel<<<dim3(32, M / 128), 256>>>(x);
    wpack_kernel<<<dim3(12, 32), 256, 0, s1>>>(W_qkv, wqkvB, 3 * DIMC);
    wpack_kernel<<<dim3(4, 32),  256, 0, s2>>>(W_proj, wprojB, DIMC);
    cudaEventRecord(evQkvW,  s1);
    cudaEventRecord(evProjW, s2);

    // 1) QKV = x @ W_qkv + b_qkv  -> per-head packed g_qkvP (Q pre-scaled)
    cudaStreamWaitEvent(0, evQkvW, 0);
    gemm_bulk_kernel<<<dim3(12, M / 128), 256, G_SMEM>>>(
        xA, wqkvB, b_qkv, nullptr, 3 * DIMC, 1);

    // 2) causal attention: all-bulk staging, paired q-tiles, single wave
    attn_f16_kernel<<<dim3(T / 256, NHEAD, BATCH), 128, AT_SMEM>>>(T);

    // 3) out = attnP @ W_proj + b_proj  (fp32 out)
    cudaStreamWaitEvent(0, evProjW, 0);
    gemm_bulk_kernel<<<dim3(4, M / 128), 256, G_SMEM>>>(
        attnP, wprojB, b_proj, out, DIMC, 0);
}